// round 1
// baseline (speedup 1.0000x reference)
#include <cuda_runtime.h>
#include <math.h>

#define D_MODEL 2048
#define NUM_HEADS 16
#define HEAD_DIM 128
#define MAX_SEQ_LEN 32768
#define SPLITS 32
#define SCALE 0.08838834764831845f   // 1/sqrt(128)

// ---------------- device scratch (no allocations allowed) ----------------
__device__ float g_q[D_MODEL];
__device__ float g_k[D_MODEL];
__device__ float g_v[D_MODEL];
__device__ float g_attn[D_MODEL];
__device__ float g_pm[NUM_HEADS * SPLITS];
__device__ float g_pl[NUM_HEADS * SPLITS];
__device__ float g_pacc[NUM_HEADS * SPLITS * HEAD_DIM];

// ---------------- K1: fused QKV matvecs (warp per output row) ------------
__global__ void qkv_kernel(const float* __restrict__ x,
                           const float* __restrict__ Wq,
                           const float* __restrict__ Wk,
                           const float* __restrict__ Wv) {
    __shared__ float xs[D_MODEL];
    int tid = threadIdx.x;
    for (int i = tid; i < D_MODEL; i += blockDim.x) xs[i] = x[i];
    __syncthreads();

    int warp = blockIdx.x * (blockDim.x >> 5) + (tid >> 5);  // 0..6143
    int lane = tid & 31;
    int mat = warp >> 11;          // 0=Wq 1=Wk 2=Wv
    int row = warp & 2047;
    const float* W = (mat == 0) ? Wq : ((mat == 1) ? Wk : Wv);
    const float4* wr = (const float4*)(W + (size_t)row * D_MODEL);

    float acc = 0.f;
#pragma unroll 4
    for (int j = lane; j < D_MODEL / 4; j += 32) {
        float4 w = wr[j];
        acc += xs[j * 4 + 0] * w.x + xs[j * 4 + 1] * w.y
             + xs[j * 4 + 2] * w.z + xs[j * 4 + 3] * w.w;
    }
#pragma unroll
    for (int o = 16; o; o >>= 1) acc += __shfl_xor_sync(0xffffffffu, acc, o);

    if (lane == 0) {
        float* dst = (mat == 0) ? g_q : ((mat == 1) ? g_k : g_v);
        dst[row] = acc;
    }
}

// ---------------- K2: split-K flash decode over past keys ----------------
// grid = NUM_HEADS * SPLITS blocks, 256 threads (8 warps, warp per key)
__global__ void attn_split_kernel(const float* __restrict__ past_k,
                                  const float* __restrict__ past_v,
                                  const int* __restrict__ ci_p) {
    int h  = blockIdx.x / SPLITS;
    int sp = blockIdx.x % SPLITS;
    int ci = *ci_p;                       // number of PAST valid keys
    int chunk  = (ci + SPLITS - 1) / SPLITS;
    int kstart = sp * chunk;
    int kend   = min(kstart + chunk, ci);

    __shared__ float qs[HEAD_DIM];
    __shared__ float wm[8], wl[8];
    __shared__ float wacc[8][HEAD_DIM];

    int tid = threadIdx.x, wid = tid >> 5, lane = tid & 31;
    if (tid < HEAD_DIM) qs[tid] = g_q[h * HEAD_DIM + tid];
    __syncthreads();

    float q0 = qs[lane * 4 + 0], q1 = qs[lane * 4 + 1];
    float q2 = qs[lane * 4 + 2], q3 = qs[lane * 4 + 3];

    float m = -INFINITY, l = 0.f;
    float4 acc = make_float4(0.f, 0.f, 0.f, 0.f);
    const size_t hoff = (size_t)h * HEAD_DIM;

    for (int key = kstart + wid; key < kend; key += 8) {
        size_t base = (size_t)key * (NUM_HEADS * HEAD_DIM) + hoff + lane * 4;
        float4 kk = *(const float4*)(past_k + base);
        float s = kk.x * q0 + kk.y * q1 + kk.z * q2 + kk.w * q3;
#pragma unroll
        for (int o = 16; o; o >>= 1) s += __shfl_xor_sync(0xffffffffu, s, o);
        s *= SCALE;
        float mn   = fmaxf(m, s);
        float corr = __expf(m - mn);
        float p    = __expf(s - mn);
        float4 vv  = *(const float4*)(past_v + base);
        acc.x = acc.x * corr + p * vv.x;
        acc.y = acc.y * corr + p * vv.y;
        acc.z = acc.z * corr + p * vv.z;
        acc.w = acc.w * corr + p * vv.w;
        l = l * corr + p;
        m = mn;
    }

    wacc[wid][lane * 4 + 0] = acc.x;
    wacc[wid][lane * 4 + 1] = acc.y;
    wacc[wid][lane * 4 + 2] = acc.z;
    wacc[wid][lane * 4 + 3] = acc.w;
    if (lane == 0) { wm[wid] = m; wl[wid] = l; }
    __syncthreads();

    if (tid < HEAD_DIM) {
        float mb = -INFINITY;
#pragma unroll
        for (int w = 0; w < 8; w++) mb = fmaxf(mb, wm[w]);
        float lb = 0.f, od = 0.f;
        if (mb != -INFINITY) {
#pragma unroll
            for (int w = 0; w < 8; w++) {
                float e = __expf(wm[w] - mb);
                lb += wl[w] * e;
                od += wacc[w][tid] * e;
            }
        }
        int idx = h * SPLITS + sp;
        g_pacc[idx * HEAD_DIM + tid] = od;
        if (tid == 0) { g_pm[idx] = mb; g_pl[idx] = lb; }
    }
}

// ---------------- K3: combine splits + new-key contribution --------------
// grid = NUM_HEADS blocks, 128 threads (tid = head-dim index)
__global__ void attn_reduce_kernel() {
    int h = blockIdx.x, tid = threadIdx.x;
    __shared__ float red[HEAD_DIM];

    float qv = g_q[h * HEAD_DIM + tid];
    float kv = g_k[h * HEAD_DIM + tid];
    red[tid] = qv * kv;
    __syncthreads();
    for (int s = 64; s; s >>= 1) {
        if (tid < s) red[tid] += red[tid + s];
        __syncthreads();
    }
    float s_new = red[0] * SCALE;   // new key is always valid (idx = cache_index < ci+1)

    float mg = s_new;
#pragma unroll
    for (int sp = 0; sp < SPLITS; sp++) mg = fmaxf(mg, g_pm[h * SPLITS + sp]);

    float en  = __expf(s_new - mg);
    float num = en * g_v[h * HEAD_DIM + tid];
    float den = en;
#pragma unroll
    for (int sp = 0; sp < SPLITS; sp++) {
        float e = __expf(g_pm[h * SPLITS + sp] - mg);
        num += e * g_pacc[(h * SPLITS + sp) * HEAD_DIM + tid];
        den += e * g_pl[h * SPLITS + sp];
    }
    g_attn[h * HEAD_DIM + tid] = num / den;
}

// ---------------- K4: output projection y = attn @ Wo.T ------------------
__global__ void proj_kernel(const float* __restrict__ Wo, float* __restrict__ y) {
    __shared__ float xs[D_MODEL];
    int tid = threadIdx.x;
    for (int i = tid; i < D_MODEL; i += blockDim.x) xs[i] = g_attn[i];
    __syncthreads();

    int row  = blockIdx.x * (blockDim.x >> 5) + (tid >> 5);
    int lane = tid & 31;
    const float4* wr = (const float4*)(Wo + (size_t)row * D_MODEL);

    float acc = 0.f;
#pragma unroll 4
    for (int j = lane; j < D_MODEL / 4; j += 32) {
        float4 w = wr[j];
        acc += xs[j * 4 + 0] * w.x + xs[j * 4 + 1] * w.y
             + xs[j * 4 + 2] * w.z + xs[j * 4 + 3] * w.w;
    }
#pragma unroll
    for (int o = 16; o; o >>= 1) acc += __shfl_xor_sync(0xffffffffu, acc, o);
    if (lane == 0) y[row] = acc;
}

// ---------------- K5: bulk cache copy, folding the new row ---------------
__global__ void copy_cache_kernel(const float4* __restrict__ pk,
                                  const float4* __restrict__ pv,
                                  float4* __restrict__ ok,
                                  float4* __restrict__ ov,
                                  const int* __restrict__ ci_p) {
    const size_t n4 = (size_t)MAX_SEQ_LEN * D_MODEL / 4;    // 16,777,216
    int ci = *ci_p;
    size_t row_lo = (size_t)ci * (D_MODEL / 4);             // 512 float4 per row
    size_t row_hi = row_lo + D_MODEL / 4;

    size_t stride = (size_t)gridDim.x * blockDim.x;
    for (size_t i = (size_t)blockIdx.x * blockDim.x + threadIdx.x; i < n4; i += stride) {
        float4 a = pk[i];
        float4 b = pv[i];
        if (i >= row_lo && i < row_hi) {
            size_t e = (i - row_lo) * 4;
            a = make_float4(g_k[e], g_k[e + 1], g_k[e + 2], g_k[e + 3]);
            b = make_float4(g_v[e], g_v[e + 1], g_v[e + 2], g_v[e + 3]);
        }
        ok[i] = a;
        ov[i] = b;
    }
}

// ---------------- launch ---------------------------------------------------
extern "C" void kernel_launch(void* const* d_in, const int* in_sizes, int n_in,
                              void* d_out, int out_size) {
    const float* x  = (const float*)d_in[0];
    const float* Wq = (const float*)d_in[1];
    const float* Wk = (const float*)d_in[2];
    const float* Wv = (const float*)d_in[3];
    const float* Wo = (const float*)d_in[4];
    const float* pk = (const float*)d_in[5];
    const float* pv = (const float*)d_in[6];
    const int*   ci = (const int*)d_in[7];

    float* y  = (float*)d_out;
    float* ok = y + D_MODEL;
    float* ov = ok + (size_t)MAX_SEQ_LEN * D_MODEL;

    // 3*2048 rows, warp per row, 8 warps/block -> 768 blocks
    qkv_kernel<<<768, 256>>>(x, Wq, Wk, Wv);
    attn_split_kernel<<<NUM_HEADS * SPLITS, 256>>>(pk, pv, ci);
    attn_reduce_kernel<<<NUM_HEADS, HEAD_DIM>>>();
    proj_kernel<<<256, 256>>>(Wo, y);
    copy_cache_kernel<<<4736, 256>>>((const float4*)pk, (const float4*)pv,
                                     (float4*)ok, (float4*)ov, ci);
}

// round 2
// speedup vs baseline: 1.1788x; 1.1788x over previous
#include <cuda_runtime.h>
#include <math.h>

#define D_MODEL 2048
#define NUM_HEADS 16
#define HEAD_DIM 128
#define MAX_SEQ_LEN 32768
#define KB 128                      // key-blocks per head (== splits per head)
#define CHUNK (MAX_SEQ_LEN / KB)    // 256 keys per block
#define SCALE 0.08838834764831845f  // 1/sqrt(128)

// ---------------- device scratch (no allocations allowed) ----------------
__device__ float g_q[D_MODEL];
__device__ float g_k[D_MODEL];
__device__ float g_v[D_MODEL];
__device__ float g_attn[D_MODEL];
__device__ float g_pm[NUM_HEADS * KB];
__device__ float g_pl[NUM_HEADS * KB];
__device__ float g_pacc[NUM_HEADS * KB * HEAD_DIM];

// ---------------- K1: fused QKV matvecs (warp per output row) ------------
__global__ void qkv_kernel(const float* __restrict__ x,
                           const float* __restrict__ Wq,
                           const float* __restrict__ Wk,
                           const float* __restrict__ Wv) {
    __shared__ float xs[D_MODEL];
    int tid = threadIdx.x;
    for (int i = tid; i < D_MODEL; i += blockDim.x) xs[i] = x[i];
    __syncthreads();

    int warp = blockIdx.x * (blockDim.x >> 5) + (tid >> 5);  // 0..6143
    int lane = tid & 31;
    int mat = warp >> 11;          // 0=Wq 1=Wk 2=Wv
    int row = warp & 2047;
    const float* W = (mat == 0) ? Wq : ((mat == 1) ? Wk : Wv);
    const float4* wr = (const float4*)(W + (size_t)row * D_MODEL);

    float acc = 0.f;
#pragma unroll 4
    for (int j = lane; j < D_MODEL / 4; j += 32) {
        float4 w = wr[j];
        acc += xs[j * 4 + 0] * w.x + xs[j * 4 + 1] * w.y
             + xs[j * 4 + 2] * w.z + xs[j * 4 + 3] * w.w;
    }
#pragma unroll
    for (int o = 16; o; o >>= 1) acc += __shfl_xor_sync(0xffffffffu, acc, o);

    if (lane == 0) {
        float* dst = (mat == 0) ? g_q : ((mat == 1) ? g_k : g_v);
        dst[row] = acc;
    }
}

// ---------------- K2: FUSED cache copy + split flash attention ------------
// grid = NUM_HEADS * KB blocks of 256 threads (8 warps, warp per key).
// Block (h, kb) copies keys [kb*CHUNK, (kb+1)*CHUNK) of head h for BOTH
// caches (folding the new row at ci), and simultaneously accumulates the
// online-softmax partial for the keys < ci. K/V are read exactly once.
__global__ void fused_copy_attn_kernel(const float4* __restrict__ pk,
                                       const float4* __restrict__ pv,
                                       float4* __restrict__ ok,
                                       float4* __restrict__ ov,
                                       const int* __restrict__ ci_p) {
    int h  = blockIdx.x / KB;
    int kb = blockIdx.x % KB;
    int ci = *ci_p;
    int kstart = kb * CHUNK;

    __shared__ float wm[8], wl[8];
    __shared__ float wacc[8][HEAD_DIM];

    int tid = threadIdx.x, wid = tid >> 5, lane = tid & 31;

    const float4* qg = (const float4*)(g_q + h * HEAD_DIM);
    float4 q = qg[lane];
    float4 foldk = ((const float4*)(g_k + h * HEAD_DIM))[lane];
    float4 foldv = ((const float4*)(g_v + h * HEAD_DIM))[lane];

    float m = -INFINITY, l = 0.f;
    float4 acc = make_float4(0.f, 0.f, 0.f, 0.f);

    const int seg_stride = NUM_HEADS * (HEAD_DIM / 4);   // 512 float4 per key row
    const int hbase = h * (HEAD_DIM / 4) + lane;

    for (int key = kstart + wid; key < kstart + CHUNK; key += 8) {
        size_t idx = (size_t)key * seg_stride + hbase;
        float4 kk, vv;
        if (key == ci) { kk = foldk; vv = foldv; }
        else           { kk = pk[idx]; vv = pv[idx]; }
        ok[idx] = kk;
        ov[idx] = vv;

        if (key < ci) {
            float s = kk.x * q.x + kk.y * q.y + kk.z * q.z + kk.w * q.w;
#pragma unroll
            for (int o = 16; o; o >>= 1) s += __shfl_xor_sync(0xffffffffu, s, o);
            s *= SCALE;
            float mn   = fmaxf(m, s);
            float corr = __expf(m - mn);
            float p    = __expf(s - mn);
            acc.x = acc.x * corr + p * vv.x;
            acc.y = acc.y * corr + p * vv.y;
            acc.z = acc.z * corr + p * vv.z;
            acc.w = acc.w * corr + p * vv.w;
            l = l * corr + p;
            m = mn;
        }
    }

    wacc[wid][lane * 4 + 0] = acc.x;
    wacc[wid][lane * 4 + 1] = acc.y;
    wacc[wid][lane * 4 + 2] = acc.z;
    wacc[wid][lane * 4 + 3] = acc.w;
    if (lane == 0) { wm[wid] = m; wl[wid] = l; }
    __syncthreads();

    if (tid < HEAD_DIM) {
        float mb = -INFINITY;
#pragma unroll
        for (int w = 0; w < 8; w++) mb = fmaxf(mb, wm[w]);
        float lb = 0.f, od = 0.f;
        if (mb != -INFINITY) {
#pragma unroll
            for (int w = 0; w < 8; w++) {
                float e = __expf(wm[w] - mb);
                lb += wl[w] * e;
                od += wacc[w][tid] * e;
            }
        }
        int idx = h * KB + kb;
        g_pacc[idx * HEAD_DIM + tid] = od;
        if (tid == 0) { g_pm[idx] = mb; g_pl[idx] = lb; }
    }
}

// ---------------- K3: combine splits + new-key contribution --------------
// grid = NUM_HEADS blocks, 128 threads (tid = head-dim index)
__global__ void attn_reduce_kernel() {
    int h = blockIdx.x, tid = threadIdx.x;
    __shared__ float red[HEAD_DIM];

    float qv = g_q[h * HEAD_DIM + tid];
    float kv = g_k[h * HEAD_DIM + tid];
    red[tid] = qv * kv;
    __syncthreads();
    for (int s = 64; s; s >>= 1) {
        if (tid < s) red[tid] += red[tid + s];
        __syncthreads();
    }
    float s_new = red[0] * SCALE;   // new key is always valid

    float mg = s_new;
#pragma unroll 8
    for (int sp = 0; sp < KB; sp++) mg = fmaxf(mg, g_pm[h * KB + sp]);

    float en  = __expf(s_new - mg);
    float num = en * g_v[h * HEAD_DIM + tid];
    float den = en;
#pragma unroll 8
    for (int sp = 0; sp < KB; sp++) {
        float e = __expf(g_pm[h * KB + sp] - mg);
        num += e * g_pacc[(h * KB + sp) * HEAD_DIM + tid];
        den += e * g_pl[h * KB + sp];
    }
    g_attn[h * HEAD_DIM + tid] = num / den;
}

// ---------------- K4: output projection y = attn @ Wo.T ------------------
// 512 blocks x 256 threads; 64 threads (2 warps) per output row.
__global__ void proj_kernel(const float* __restrict__ Wo, float* __restrict__ y) {
    __shared__ float xs[D_MODEL];
    __shared__ float part[8];
    int tid = threadIdx.x;
    for (int i = tid; i < D_MODEL; i += blockDim.x) xs[i] = g_attn[i];
    __syncthreads();

    int pair = tid >> 6;                 // 0..3 : which row within block
    int sub  = tid & 63;                 // 0..63: thread within row group
    int lane = tid & 31;
    int row  = blockIdx.x * 4 + pair;
    const float4* wr = (const float4*)(Wo + (size_t)row * D_MODEL);

    float acc = 0.f;
#pragma unroll 4
    for (int j = sub; j < D_MODEL / 4; j += 64) {
        float4 w = wr[j];
        acc += xs[j * 4 + 0] * w.x + xs[j * 4 + 1] * w.y
             + xs[j * 4 + 2] * w.z + xs[j * 4 + 3] * w.w;
    }
#pragma unroll
    for (int o = 16; o; o >>= 1) acc += __shfl_xor_sync(0xffffffffu, acc, o);
    if (lane == 0) part[tid >> 5] = acc;
    __syncthreads();
    if (sub == 0) y[row] = part[pair * 2] + part[pair * 2 + 1];
}

// ---------------- launch ---------------------------------------------------
extern "C" void kernel_launch(void* const* d_in, const int* in_sizes, int n_in,
                              void* d_out, int out_size) {
    const float* x  = (const float*)d_in[0];
    const float* Wq = (const float*)d_in[1];
    const float* Wk = (const float*)d_in[2];
    const float* Wv = (const float*)d_in[3];
    const float* Wo = (const float*)d_in[4];
    const float* pk = (const float*)d_in[5];
    const float* pv = (const float*)d_in[6];
    const int*   ci = (const int*)d_in[7];

    float* y  = (float*)d_out;
    float* ok = y + D_MODEL;
    float* ov = ok + (size_t)MAX_SEQ_LEN * D_MODEL;

    qkv_kernel<<<768, 256>>>(x, Wq, Wk, Wv);
    fused_copy_attn_kernel<<<NUM_HEADS * KB, 256>>>(
        (const float4*)pk, (const float4*)pv,
        (float4*)ok, (float4*)ov, ci);
    attn_reduce_kernel<<<NUM_HEADS, HEAD_DIM>>>();
    proj_kernel<<<512, 256>>>(Wo, y);
}

// round 3
// speedup vs baseline: 1.2630x; 1.0714x over previous
#include <cuda_runtime.h>
#include <math.h>

#define D_MODEL 2048
#define NUM_HEADS 16
#define HEAD_DIM 128
#define MAX_SEQ_LEN 32768
#define KB 64                       // key-blocks per head (splits per head)
#define CHUNK (MAX_SEQ_LEN / KB)    // 512 keys per block
#define HALF (CHUNK / 2)            // 256 keys per stream
#define SCALE 0.08838834764831845f  // 1/sqrt(128)

// ---------------- device scratch (no allocations allowed) ----------------
__device__ float g_q[D_MODEL];
__device__ float g_k[D_MODEL];
__device__ float g_v[D_MODEL];
__device__ float g_attn[D_MODEL];
__device__ float g_pm[NUM_HEADS * KB];
__device__ float g_pl[NUM_HEADS * KB];
__device__ float g_pacc[NUM_HEADS * KB * HEAD_DIM];

// ---------------- K1: fused QKV matvecs (warp per output row) ------------
__global__ __launch_bounds__(256) void qkv_kernel(const float* __restrict__ x,
                                                  const float* __restrict__ Wq,
                                                  const float* __restrict__ Wk,
                                                  const float* __restrict__ Wv) {
    __shared__ float xs[D_MODEL];
    int tid = threadIdx.x;
    {
        float4* xs4 = (float4*)xs;
        const float4* x4 = (const float4*)x;
#pragma unroll
        for (int i = 0; i < 2; i++) xs4[tid + i * 256] = x4[tid + i * 256];
    }
    __syncthreads();

    int warp = blockIdx.x * 8 + (tid >> 5);  // 0..6143
    int lane = tid & 31;
    int mat = warp >> 11;          // 0=Wq 1=Wk 2=Wv
    int row = warp & 2047;
    const float* W = (mat == 0) ? Wq : ((mat == 1) ? Wk : Wv);
    const float4* wr = (const float4*)(W + (size_t)row * D_MODEL);

    float acc = 0.f;
#pragma unroll
    for (int it = 0; it < 16; it++) {
        int j = lane + it * 32;
        float4 w = wr[j];
        acc += xs[j * 4 + 0] * w.x + xs[j * 4 + 1] * w.y
             + xs[j * 4 + 2] * w.z + xs[j * 4 + 3] * w.w;
    }
#pragma unroll
    for (int o = 16; o; o >>= 1) acc += __shfl_xor_sync(0xffffffffu, acc, o);

    if (lane == 0) {
        float* dst = (mat == 0) ? g_q : ((mat == 1) ? g_k : g_v);
        dst[row] = acc;
    }
}

// ---------------- K2: FUSED cache copy + split flash attention ------------
// grid = NUM_HEADS * KB = 1024 blocks of 256 threads => single resident wave.
// Block (h, kb) copies keys [kb*CHUNK, (kb+1)*CHUNK) of head h for BOTH
// caches (folding the new row at ci) and accumulates the online-softmax
// partial for keys < ci. Each warp runs TWO independent key streams per
// iteration so the shuffle-reduce chains interleave.
__global__ __launch_bounds__(256) void fused_copy_attn_kernel(
        const float4* __restrict__ pk,
        const float4* __restrict__ pv,
        float4* __restrict__ ok,
        float4* __restrict__ ov,
        const int* __restrict__ ci_p) {
    int h  = blockIdx.x / KB;
    int kb = blockIdx.x % KB;
    int ci = *ci_p;
    int kstart = kb * CHUNK;

    __shared__ float wm[8], wl[8];
    __shared__ float wacc[8][HEAD_DIM];

    int tid = threadIdx.x, wid = tid >> 5, lane = tid & 31;

    float4 q     = ((const float4*)(g_q + h * HEAD_DIM))[lane];
    float4 foldk = ((const float4*)(g_k + h * HEAD_DIM))[lane];
    float4 foldv = ((const float4*)(g_v + h * HEAD_DIM))[lane];

    float m = -INFINITY, l = 0.f;
    float4 acc = make_float4(0.f, 0.f, 0.f, 0.f);

    const int seg_stride = NUM_HEADS * (HEAD_DIM / 4);   // 512 float4 per key row
    const int hbase = h * (HEAD_DIM / 4) + lane;

    for (int it = 0; it < HALF / 8; it++) {
        int keyA = kstart + wid + it * 8;
        int keyB = keyA + HALF;
        size_t ia = (size_t)keyA * seg_stride + hbase;
        size_t ib = (size_t)keyB * seg_stride + hbase;

        float4 kA, vA, kB, vB;
        if (keyA == ci) { kA = foldk; vA = foldv; }
        else            { kA = __ldcs(pk + ia); vA = __ldcs(pv + ia); }
        if (keyB == ci) { kB = foldk; vB = foldv; }
        else            { kB = __ldcs(pk + ib); vB = __ldcs(pv + ib); }
        __stcs(ok + ia, kA); __stcs(ov + ia, vA);
        __stcs(ok + ib, kB); __stcs(ov + ib, vB);

        bool aval = keyA < ci;
        bool bval = keyB < ci;
        if (aval || bval) {
            float sA = kA.x * q.x + kA.y * q.y + kA.z * q.z + kA.w * q.w;
            float sB = kB.x * q.x + kB.y * q.y + kB.z * q.z + kB.w * q.w;
#pragma unroll
            for (int o = 16; o; o >>= 1) {
                sA += __shfl_xor_sync(0xffffffffu, sA, o);
                sB += __shfl_xor_sync(0xffffffffu, sB, o);
            }
            sA = aval ? sA * SCALE : -INFINITY;
            sB = bval ? sB * SCALE : -INFINITY;
            float mn   = fmaxf(m, fmaxf(sA, sB));
            float corr = __expf(m - mn);
            float pA   = __expf(sA - mn);
            float pB   = __expf(sB - mn);
            acc.x = acc.x * corr + pA * vA.x + pB * vB.x;
            acc.y = acc.y * corr + pA * vA.y + pB * vB.y;
            acc.z = acc.z * corr + pA * vA.z + pB * vB.z;
            acc.w = acc.w * corr + pA * vA.w + pB * vB.w;
            l = l * corr + pA + pB;
            m = mn;
        }
    }

    wacc[wid][lane * 4 + 0] = acc.x;
    wacc[wid][lane * 4 + 1] = acc.y;
    wacc[wid][lane * 4 + 2] = acc.z;
    wacc[wid][lane * 4 + 3] = acc.w;
    if (lane == 0) { wm[wid] = m; wl[wid] = l; }
    __syncthreads();

    if (tid < HEAD_DIM) {
        float mb = -INFINITY;
#pragma unroll
        for (int w = 0; w < 8; w++) mb = fmaxf(mb, wm[w]);
        float lb = 0.f, od = 0.f;
        if (mb != -INFINITY) {
#pragma unroll
            for (int w = 0; w < 8; w++) {
                float e = __expf(wm[w] - mb);
                lb += wl[w] * e;
                od += wacc[w][tid] * e;
            }
        }
        int idx = h * KB + kb;
        g_pacc[idx * HEAD_DIM + tid] = od;
        if (tid == 0) { g_pm[idx] = mb; g_pl[idx] = lb; }
    }
}

// ---------------- K3: combine splits + new-key contribution --------------
// grid = NUM_HEADS blocks, 128 threads (tid = head-dim index)
__global__ __launch_bounds__(HEAD_DIM) void attn_reduce_kernel() {
    int h = blockIdx.x, tid = threadIdx.x;
    __shared__ float red[HEAD_DIM];

    float qv = g_q[h * HEAD_DIM + tid];
    float kv = g_k[h * HEAD_DIM + tid];
    red[tid] = qv * kv;
    __syncthreads();
    for (int s = 64; s; s >>= 1) {
        if (tid < s) red[tid] += red[tid + s];
        __syncthreads();
    }
    float s_new = red[0] * SCALE;   // new key is always valid

    float mg = s_new;
#pragma unroll 8
    for (int sp = 0; sp < KB; sp++) mg = fmaxf(mg, g_pm[h * KB + sp]);

    float en  = __expf(s_new - mg);
    float num = en * g_v[h * HEAD_DIM + tid];
    float den = en;
#pragma unroll 8
    for (int sp = 0; sp < KB; sp++) {
        float e = __expf(g_pm[h * KB + sp] - mg);
        num += e * g_pacc[(h * KB + sp) * HEAD_DIM + tid];
        den += e * g_pl[h * KB + sp];
    }
    g_attn[h * HEAD_DIM + tid] = num / den;
}

// ---------------- K4: output projection y = attn @ Wo.T ------------------
// 512 blocks x 256 threads; 64 threads (2 warps) per output row.
__global__ __launch_bounds__(256) void proj_kernel(const float* __restrict__ Wo,
                                                   float* __restrict__ y) {
    __shared__ float xs[D_MODEL];
    __shared__ float part[8];
    int tid = threadIdx.x;
    {
        float4* xs4 = (float4*)xs;
        const float4* a4 = (const float4*)g_attn;
#pragma unroll
        for (int i = 0; i < 2; i++) xs4[tid + i * 256] = a4[tid + i * 256];
    }
    __syncthreads();

    int pair = tid >> 6;                 // 0..3 : which row within block
    int sub  = tid & 63;                 // 0..63: thread within row group
    int lane = tid & 31;
    int row  = blockIdx.x * 4 + pair;
    const float4* wr = (const float4*)(Wo + (size_t)row * D_MODEL);

    float acc = 0.f;
#pragma unroll
    for (int it = 0; it < 8; it++) {
        int j = sub + it * 64;
        float4 w = wr[j];
        acc += xs[j * 4 + 0] * w.x + xs[j * 4 + 1] * w.y
             + xs[j * 4 + 2] * w.z + xs[j * 4 + 3] * w.w;
    }
#pragma unroll
    for (int o = 16; o; o >>= 1) acc += __shfl_xor_sync(0xffffffffu, acc, o);
    if (lane == 0) part[tid >> 5] = acc;
    __syncthreads();
    if (sub == 0) y[row] = part[pair * 2] + part[pair * 2 + 1];
}

// ---------------- launch ---------------------------------------------------
extern "C" void kernel_launch(void* const* d_in, const int* in_sizes, int n_in,
                              void* d_out, int out_size) {
    const float* x  = (const float*)d_in[0];
    const float* Wq = (const float*)d_in[1];
    const float* Wk = (const float*)d_in[2];
    const float* Wv = (const float*)d_in[3];
    const float* Wo = (const float*)d_in[4];
    const float* pk = (const float*)d_in[5];
    const float* pv = (const float*)d_in[6];
    const int*   ci = (const int*)d_in[7];

    float* y  = (float*)d_out;
    float* ok = y + D_MODEL;
    float* ov = ok + (size_t)MAX_SEQ_LEN * D_MODEL;

    qkv_kernel<<<768, 256>>>(x, Wq, Wk, Wv);
    fused_copy_attn_kernel<<<NUM_HEADS * KB, 256>>>(
        (const float4*)pk, (const float4*)pv,
        (float4*)ok, (float4*)ov, ci);
    attn_reduce_kernel<<<NUM_HEADS, HEAD_DIM>>>();
    proj_kernel<<<512, 256>>>(Wo, y);
}

// round 4
// speedup vs baseline: 1.2774x; 1.0114x over previous
#include <cuda_runtime.h>
#include <math.h>

#define D_MODEL 2048
#define NUM_HEADS 16
#define HEAD_DIM 128
#define MAX_SEQ_LEN 32768
#define KB 64                       // key-blocks per head (splits per head)
#define CHUNK (MAX_SEQ_LEN / KB)    // 512 keys per block
#define HALF (CHUNK / 2)            // 256 keys per stream
#define SCALE 0.08838834764831845f  // 1/sqrt(128)

// ---------------- device scratch (no allocations allowed) ----------------
__device__ float g_q[D_MODEL];
__device__ float g_k[D_MODEL];
__device__ float g_v[D_MODEL];
__device__ float g_attn[D_MODEL];
__device__ float g_pm[NUM_HEADS * KB];
__device__ float g_pl[NUM_HEADS * KB];
__device__ float g_pacc[NUM_HEADS * KB * HEAD_DIM];

// ---------------- register-blocked 64-thread row dot ----------------------
// 8 float4 loads batched into registers BEFORE any FMA => MLP = 8/thread.
__device__ __forceinline__ float row_dot64(const float4* __restrict__ wr,
                                           const float* __restrict__ xs,
                                           int sub) {
    float4 w[8];
#pragma unroll
    for (int it = 0; it < 8; it++) w[it] = __ldcs(wr + sub + it * 64);
    float acc = 0.f;
#pragma unroll
    for (int it = 0; it < 8; it++) {
        int j = sub + it * 64;
        acc += xs[j * 4 + 0] * w[it].x + xs[j * 4 + 1] * w[it].y
             + xs[j * 4 + 2] * w[it].z + xs[j * 4 + 3] * w[it].w;
    }
#pragma unroll
    for (int o = 16; o; o >>= 1) acc += __shfl_xor_sync(0xffffffffu, acc, o);
    return acc;
}

// ---------------- K1: fused QKV matvecs (64 threads per output row) -------
// 6144 rows (Wq|Wk|Wv) * 64 threads = 1536 blocks of 256.
__global__ __launch_bounds__(256) void qkv_kernel(const float* __restrict__ x,
                                                  const float* __restrict__ Wq,
                                                  const float* __restrict__ Wk,
                                                  const float* __restrict__ Wv) {
    __shared__ float xs[D_MODEL];
    __shared__ float part[8];
    int tid = threadIdx.x;
    {
        float4* xs4 = (float4*)xs;
        const float4* x4 = (const float4*)x;
#pragma unroll
        for (int i = 0; i < 2; i++) xs4[tid + i * 256] = x4[tid + i * 256];
    }
    __syncthreads();

    int grow = blockIdx.x * 4 + (tid >> 6);   // 0..6143 global row
    int sub  = tid & 63;
    int lane = tid & 31;
    int mat  = grow >> 11;                    // 0=Wq 1=Wk 2=Wv (uniform per block)
    int row  = grow & 2047;
    const float* W = (mat == 0) ? Wq : ((mat == 1) ? Wk : Wv);
    const float4* wr = (const float4*)(W + (size_t)row * D_MODEL);

    float acc = row_dot64(wr, xs, sub);
    if (lane == 0) part[tid >> 5] = acc;
    __syncthreads();
    if (sub == 0) {
        float* dst = (mat == 0) ? g_q : ((mat == 1) ? g_k : g_v);
        int p = (tid >> 5);
        dst[row] = part[p] + part[p + 1];
    }
}

// ---------------- K2: FUSED cache copy + split flash attention ------------
// grid = NUM_HEADS * KB = 1024 blocks of 256 threads => single resident wave.
__global__ __launch_bounds__(256) void fused_copy_attn_kernel(
        const float4* __restrict__ pk,
        const float4* __restrict__ pv,
        float4* __restrict__ ok,
        float4* __restrict__ ov,
        const int* __restrict__ ci_p) {
    int h  = blockIdx.x / KB;
    int kb = blockIdx.x % KB;
    int ci = *ci_p;
    int kstart = kb * CHUNK;

    __shared__ float wm[8], wl[8];
    __shared__ float wacc[8][HEAD_DIM];

    int tid = threadIdx.x, wid = tid >> 5, lane = tid & 31;

    float4 q     = ((const float4*)(g_q + h * HEAD_DIM))[lane];
    float4 foldk = ((const float4*)(g_k + h * HEAD_DIM))[lane];
    float4 foldv = ((const float4*)(g_v + h * HEAD_DIM))[lane];

    float m = -INFINITY, l = 0.f;
    float4 acc = make_float4(0.f, 0.f, 0.f, 0.f);

    const int seg_stride = NUM_HEADS * (HEAD_DIM / 4);   // 512 float4 per key row
    const int hbase = h * (HEAD_DIM / 4) + lane;

    for (int it = 0; it < HALF / 8; it++) {
        int keyA = kstart + wid + it * 8;
        int keyB = keyA + HALF;
        size_t ia = (size_t)keyA * seg_stride + hbase;
        size_t ib = (size_t)keyB * seg_stride + hbase;

        float4 kA, vA, kB, vB;
        if (keyA == ci) { kA = foldk; vA = foldv; }
        else            { kA = __ldcs(pk + ia); vA = __ldcs(pv + ia); }
        if (keyB == ci) { kB = foldk; vB = foldv; }
        else            { kB = __ldcs(pk + ib); vB = __ldcs(pv + ib); }
        __stcs(ok + ia, kA); __stcs(ov + ia, vA);
        __stcs(ok + ib, kB); __stcs(ov + ib, vB);

        bool aval = keyA < ci;
        bool bval = keyB < ci;
        if (aval || bval) {
            float sA = kA.x * q.x + kA.y * q.y + kA.z * q.z + kA.w * q.w;
            float sB = kB.x * q.x + kB.y * q.y + kB.z * q.z + kB.w * q.w;
#pragma unroll
            for (int o = 16; o; o >>= 1) {
                sA += __shfl_xor_sync(0xffffffffu, sA, o);
                sB += __shfl_xor_sync(0xffffffffu, sB, o);
            }
            sA = aval ? sA * SCALE : -INFINITY;
            sB = bval ? sB * SCALE : -INFINITY;
            float mn   = fmaxf(m, fmaxf(sA, sB));
            float corr = __expf(m - mn);
            float pA   = __expf(sA - mn);
            float pB   = __expf(sB - mn);
            acc.x = acc.x * corr + pA * vA.x + pB * vB.x;
            acc.y = acc.y * corr + pA * vA.y + pB * vB.y;
            acc.z = acc.z * corr + pA * vA.z + pB * vB.z;
            acc.w = acc.w * corr + pA * vA.w + pB * vB.w;
            l = l * corr + pA + pB;
            m = mn;
        }
    }

    wacc[wid][lane * 4 + 0] = acc.x;
    wacc[wid][lane * 4 + 1] = acc.y;
    wacc[wid][lane * 4 + 2] = acc.z;
    wacc[wid][lane * 4 + 3] = acc.w;
    if (lane == 0) { wm[wid] = m; wl[wid] = l; }
    __syncthreads();

    if (tid < HEAD_DIM) {
        float mb = -INFINITY;
#pragma unroll
        for (int w = 0; w < 8; w++) mb = fmaxf(mb, wm[w]);
        float lb = 0.f, od = 0.f;
        if (mb != -INFINITY) {
#pragma unroll
            for (int w = 0; w < 8; w++) {
                float e = __expf(wm[w] - mb);
                lb += wl[w] * e;
                od += wacc[w][tid] * e;
            }
        }
        int idx = h * KB + kb;
        g_pacc[idx * HEAD_DIM + tid] = od;
        if (tid == 0) { g_pm[idx] = mb; g_pl[idx] = lb; }
    }
}

// ---------------- K3: combine splits + new-key contribution --------------
__global__ __launch_bounds__(HEAD_DIM) void attn_reduce_kernel() {
    int h = blockIdx.x, tid = threadIdx.x;
    __shared__ float red[HEAD_DIM];

    float qv = g_q[h * HEAD_DIM + tid];
    float kv = g_k[h * HEAD_DIM + tid];
    red[tid] = qv * kv;
    __syncthreads();
    for (int s = 64; s; s >>= 1) {
        if (tid < s) red[tid] += red[tid + s];
        __syncthreads();
    }
    float s_new = red[0] * SCALE;   // new key is always valid

    float mg = s_new;
#pragma unroll 8
    for (int sp = 0; sp < KB; sp++) mg = fmaxf(mg, g_pm[h * KB + sp]);

    float en  = __expf(s_new - mg);
    float num = en * g_v[h * HEAD_DIM + tid];
    float den = en;
#pragma unroll 8
    for (int sp = 0; sp < KB; sp++) {
        float e = __expf(g_pm[h * KB + sp] - mg);
        num += e * g_pacc[(h * KB + sp) * HEAD_DIM + tid];
        den += e * g_pl[h * KB + sp];
    }
    g_attn[h * HEAD_DIM + tid] = num / den;
}

// ---------------- K4: output projection y = attn @ Wo.T ------------------
// 512 blocks x 256 threads; 64 threads (2 warps) per output row.
__global__ __launch_bounds__(256) void proj_kernel(const float* __restrict__ Wo,
                                                   float* __restrict__ y) {
    __shared__ float xs[D_MODEL];
    __shared__ float part[8];
    int tid = threadIdx.x;
    {
        float4* xs4 = (float4*)xs;
        const float4* a4 = (const float4*)g_attn;
#pragma unroll
        for (int i = 0; i < 2; i++) xs4[tid + i * 256] = a4[tid + i * 256];
    }
    __syncthreads();

    int sub  = tid & 63;
    int lane = tid & 31;
    int row  = blockIdx.x * 4 + (tid >> 6);
    const float4* wr = (const float4*)(Wo + (size_t)row * D_MODEL);

    float acc = row_dot64(wr, xs, sub);
    if (lane == 0) part[tid >> 5] = acc;
    __syncthreads();
    if (sub == 0) {
        int p = (tid >> 5);
        y[row] = part[p] + part[p + 1];
    }
}

// ---------------- launch ---------------------------------------------------
extern "C" void kernel_launch(void* const* d_in, const int* in_sizes, int n_in,
                              void* d_out, int out_size) {
    const float* x  = (const float*)d_in[0];
    const float* Wq = (const float*)d_in[1];
    const float* Wk = (const float*)d_in[2];
    const float* Wv = (const float*)d_in[3];
    const float* Wo = (const float*)d_in[4];
    const float* pk = (const float*)d_in[5];
    const float* pv = (const float*)d_in[6];
    const int*   ci = (const int*)d_in[7];

    float* y  = (float*)d_out;
    float* ok = y + D_MODEL;
    float* ov = ok + (size_t)MAX_SEQ_LEN * D_MODEL;

    qkv_kernel<<<1536, 256>>>(x, Wq, Wk, Wv);
    fused_copy_attn_kernel<<<NUM_HEADS * KB, 256>>>(
        (const float4*)pk, (const float4*)pv,
        (float4*)ok, (float4*)ov, ci);
    attn_reduce_kernel<<<NUM_HEADS, HEAD_DIM>>>();
    proj_kernel<<<512, 256>>>(Wo, y);
}